// round 5
// baseline (speedup 1.0000x reference)
#include <cuda_runtime.h>
#include <cuda_bf16.h>

// Problem constants (from reference): B=32, T=512, D=768, dur in [0,8]
#define LR_B 32
#define LR_T 512
#define LR_D 768
#define TMAX 4096          // max possible t_out = 512 * round(8.0) = 4096
#define NBLK 1184          // persistent grid: 148 SMs x 8 blocks

// Scratch (no cudaMalloc allowed)
__device__ int g_idx[LR_B * TMAX];  // g_idx[b*TMAX + t] = source row for output row t
__device__ int g_tot[LR_B];

// ---------------------------------------------------------------------------
// Kernel 1: per-batch scan + index-map scatter.
// One block per batch, 128 threads. Warp 0 computes the inclusive cumsum of
// rounded durations (register scan + shfl); then all 128 threads scatter the
// source-row id s into g_idx[cum[s-1] .. cum[s]).
// ---------------------------------------------------------------------------
__global__ void __launch_bounds__(128) lr_scan_kernel(const float* __restrict__ dur) {
    __shared__ float sd[LR_T];
    __shared__ int   sc[LR_T + 1];   // exclusive-style: sc[s]..sc[s+1] = span of row s
    const int b   = blockIdx.x;
    const int tid = threadIdx.x;

    for (int i = tid; i < LR_T; i += 128) sd[i] = dur[b * LR_T + i];
    __syncthreads();

    if (tid < 32) {
        const int lane = tid;
        int v[16];
        int run = 0;
        #pragma unroll
        for (int i = 0; i < 16; ++i) {
            float d = sd[lane * 16 + i];
            run += (int)floorf(fmaxf(d, 0.0f) + 0.5f);  // same fp ops as reference
            v[i] = run;
        }
        // exclusive warp-scan of lane totals
        int total = run;
        #pragma unroll
        for (int s = 1; s < 32; s <<= 1) {
            int n = __shfl_up_sync(0xffffffff, total, s);
            if (lane >= s) total += n;
        }
        const int off = total - run;
        #pragma unroll
        for (int i = 0; i < 16; ++i) sc[lane * 16 + i + 1] = v[i] + off;
        if (lane == 0)  sc[0] = 0;
        if (lane == 31) g_tot[b] = v[15] + off;
    }
    __syncthreads();

    // Scatter source-row ids into the index map.
    int* idxp = g_idx + b * TMAX;
    for (int s = tid; s < LR_T; s += 128) {
        const int lo = sc[s], hi = sc[s + 1];
        for (int t = lo; t < hi; ++t) idxp[t] = s;
    }
}

// ---------------------------------------------------------------------------
// Kernel 2: persistent, perfectly balanced gather.
// Each block owns a contiguous chunk of flattened output rows r = b*t_out + t.
// Per row: one broadcast idx load (L1-hot), x-row reload only when idx changes
// (L2-resident), one streaming float4 store per thread. Tail rows (t >= tot)
// store zeros (output is 0xAA-poisoned). No search, no atomics, no barriers.
// ---------------------------------------------------------------------------
__global__ void __launch_bounds__(192) lr_expand_kernel(
    const float* __restrict__ x,
    float* __restrict__ out,
    int t_out, int chunk)
{
    const int tid = threadIdx.x;
    const long rows_total = (long)LR_B * t_out;
    long r  = (long)blockIdx.x * chunk;
    if (r >= rows_total) return;
    const long r1 = min(r + (long)chunk, rows_total);

    int b = (int)(r / t_out);
    int t = (int)(r - (long)b * t_out);
    int tot = g_tot[b];
    const int* idxp = g_idx + b * TMAX;

    int cur = -1;
    float4 v = make_float4(0.f, 0.f, 0.f, 0.f);
    float4* ob = (float4*)out + r * (LR_D / 4) + tid;

    // Prefetch first idx
    int idx_n = (t < tot) ? __ldg(idxp + t) : -1;

    for (; r < r1; ++r) {
        const int idx = idx_n;
        const bool valid = (t < tot);

        // advance row cursor + prefetch next idx (independent of this row's store)
        int t2 = t + 1, b2 = b, tot2 = tot;
        const int* idxp2 = idxp;
        if (t2 == t_out) {
            t2 = 0; b2 = b + 1;
            if (b2 < LR_B) { tot2 = g_tot[b2]; idxp2 = g_idx + b2 * TMAX; }
        }
        idx_n = (r + 1 < r1 && t2 < tot2) ? __ldg(idxp2 + t2) : -1;

        float4 w;
        if (valid) {
            if (idx != cur) {
                cur = idx;
                const float4* xq = (const float4*)(x + ((size_t)b * LR_T + idx) * LR_D) + tid;
                v = __ldg(xq);
            }
            w = v;
        } else {
            w = make_float4(0.f, 0.f, 0.f, 0.f);
        }
        asm volatile("st.global.cs.v4.f32 [%0], {%1,%2,%3,%4};"
                     :: "l"(ob), "f"(w.x), "f"(w.y), "f"(w.z), "f"(w.w)
                     : "memory");
        ob += LR_D / 4;

        // commit cursor advance; reset x-row cache on batch change
        if (t2 == 0 && t != 0) cur = -1;
        t = t2; b = b2; tot = tot2; idxp = idxp2;
    }
}

// ---------------------------------------------------------------------------
extern "C" void kernel_launch(void* const* d_in, const int* in_sizes, int n_in,
                              void* d_out, int out_size) {
    const float* x   = (const float*)d_in[0];   // [B, T, D] f32
    const float* dur = (const float*)d_in[1];   // [B, T]    f32
    float* out = (float*)d_out;                 // [B, t_out, D] f32

    const int t_out = out_size / (LR_B * LR_D);
    const long rows_total = (long)LR_B * t_out;
    const int chunk = (int)((rows_total + NBLK - 1) / NBLK);

    lr_scan_kernel<<<LR_B, 128>>>(dur);
    lr_expand_kernel<<<NBLK, 192>>>(x, out, t_out, chunk);
}